// round 1
// baseline (speedup 1.0000x reference)
#include <cuda_runtime.h>
#include <cuda_fp16.h>
#include <cstdint>

#define BATCHES 16
#define NPTS    1024
#define DIMS    1024
#define EPS_SK  1e-3f
#define MAXIT   100

// ---------------- scratch (static device globals; no runtime alloc) --------
__device__ __half  d_C [BATCHES * NPTS * NPTS];   // C[b][n][m]  (32 MB)
__device__ __half  d_CT[BATCHES * NPTS * NPTS];   // C^T[b][m][n] (32 MB)
__device__ float   d_u[BATCHES * NPTS];
__device__ float   d_v[BATCHES * NPTS];
__device__ float   d_invnx[BATCHES * NPTS];
__device__ float   d_invny[BATCHES * NPTS];
__device__ unsigned d_maxbits;                    // positive-float max as bits
__device__ unsigned d_barcnt;                     // monotonic grid barrier

// ---------------- init: reset per-replay state -----------------------------
__global__ void init_kernel(float* out) {
    int i = blockIdx.x * blockDim.x + threadIdx.x;
    if (i < BATCHES * NPTS) {
        d_u[i] = 1.0f / NPTS;
        d_v[i] = 1.0f / NPTS;
    }
    if (i == 0) {
        d_maxbits = 0u;
        d_barcnt  = 0u;
        out[0]    = 0.0f;
    }
}

// ---------------- inverse L2 norms of rows ---------------------------------
// grid 4096 x 256: warp per row; rows 0..16383 -> x, 16384..32767 -> y
__global__ void norm_kernel(const float* __restrict__ x,
                            const float* __restrict__ y) {
    int gw   = blockIdx.x * 8 + (threadIdx.x >> 5);
    int lane = threadIdx.x & 31;
    const float* src;
    float* dst;
    if (gw < BATCHES * NPTS) { src = x + (size_t)gw * DIMS;                     dst = d_invnx + gw; }
    else                     { src = y + (size_t)(gw - BATCHES * NPTS) * DIMS;  dst = d_invny + (gw - BATCHES * NPTS); }
    const float4* p = (const float4*)src;
    float ss = 0.0f;
#pragma unroll
    for (int k = 0; k < 8; k++) {
        float4 f = p[lane + 32 * k];
        ss += f.x * f.x + f.y * f.y + f.z * f.z + f.w * f.w;
    }
#pragma unroll
    for (int o = 16; o; o >>= 1) ss += __shfl_xor_sync(0xffffffffu, ss, o);
    if (lane == 0) *dst = 1.0f / fmaxf(sqrtf(ss), 1e-12f);
}

// ---------------- cost GEMM: cost = 1 - (x.y) * invnx * invny --------------
// 128x128 block tile, 256 threads, 8x8 micro-tile, k-step 8 (NT gemm).
// Writes fp16 C and CT, atomicMax of fp32 cost.
__global__ void __launch_bounds__(256)
gemm_cost_kernel(const float* __restrict__ x, const float* __restrict__ y) {
    __shared__ float As[8][132];   // [k][n]
    __shared__ float Bs[8][132];   // [k][m]
    __shared__ float s_wmax[8];

    const int bz = blockIdx.z;
    const int m0 = blockIdx.x * 128;
    const int n0 = blockIdx.y * 128;
    const int tid  = threadIdx.x;
    const int tx   = tid & 15;      // m micro-tile
    const int ty   = tid >> 4;      // n micro-tile
    const int lrow = tid >> 1;      // 0..127 load row
    const int lhalf = tid & 1;      // which float4 of the 8-wide k slice

    const float* xb = x + ((size_t)bz << 20);
    const float* yb = y + ((size_t)bz << 20);

    float acc[8][8];
#pragma unroll
    for (int i = 0; i < 8; i++)
#pragma unroll
        for (int j = 0; j < 8; j++) acc[i][j] = 0.0f;

    for (int k0 = 0; k0 < DIMS; k0 += 8) {
        float4 fa = *(const float4*)(xb + (size_t)(n0 + lrow) * DIMS + k0 + lhalf * 4);
        float4 fb = *(const float4*)(yb + (size_t)(m0 + lrow) * DIMS + k0 + lhalf * 4);
        As[lhalf * 4 + 0][lrow] = fa.x; As[lhalf * 4 + 1][lrow] = fa.y;
        As[lhalf * 4 + 2][lrow] = fa.z; As[lhalf * 4 + 3][lrow] = fa.w;
        Bs[lhalf * 4 + 0][lrow] = fb.x; Bs[lhalf * 4 + 1][lrow] = fb.y;
        Bs[lhalf * 4 + 2][lrow] = fb.z; Bs[lhalf * 4 + 3][lrow] = fb.w;
        __syncthreads();
#pragma unroll
        for (int kk = 0; kk < 8; kk++) {
            float4 a0 = *(const float4*)&As[kk][ty * 8];
            float4 a1 = *(const float4*)&As[kk][ty * 8 + 4];
            float4 b0 = *(const float4*)&Bs[kk][tx * 8];
            float4 b1 = *(const float4*)&Bs[kk][tx * 8 + 4];
            float a[8] = {a0.x, a0.y, a0.z, a0.w, a1.x, a1.y, a1.z, a1.w};
            float b[8] = {b0.x, b0.y, b0.z, b0.w, b1.x, b1.y, b1.z, b1.w};
#pragma unroll
            for (int i = 0; i < 8; i++)
#pragma unroll
                for (int j = 0; j < 8; j++) acc[i][j] = fmaf(a[i], b[j], acc[i][j]);
        }
        __syncthreads();
    }

    // epilogue: cost = 1 - acc * invnx * invny  (in place)
    float inx[8], iny[8];
#pragma unroll
    for (int i = 0; i < 8; i++) inx[i] = d_invnx[bz * NPTS + n0 + ty * 8 + i];
#pragma unroll
    for (int j = 0; j < 8; j++) iny[j] = d_invny[bz * NPTS + m0 + tx * 8 + j];

    float mx = -1e30f;
#pragma unroll
    for (int i = 0; i < 8; i++)
#pragma unroll
        for (int j = 0; j < 8; j++) {
            float c = 1.0f - acc[i][j] * inx[i] * iny[j];
            acc[i][j] = c;
            mx = fmaxf(mx, c);
        }

    const size_t base = (size_t)bz << 20;
    // C rows: 8 contiguous halves per store
#pragma unroll
    for (int i = 0; i < 8; i++) {
        __half h[8];
#pragma unroll
        for (int j = 0; j < 8; j++) h[j] = __float2half_rn(acc[i][j]);
        *(uint4*)(d_C + base + (size_t)(n0 + ty * 8 + i) * NPTS + m0 + tx * 8) = *(uint4*)h;
    }
    // CT rows
#pragma unroll
    for (int j = 0; j < 8; j++) {
        __half h[8];
#pragma unroll
        for (int i = 0; i < 8; i++) h[i] = __float2half_rn(acc[i][j]);
        *(uint4*)(d_CT + base + (size_t)(m0 + tx * 8 + j) * NPTS + n0 + ty * 8) = *(uint4*)h;
    }

    // block max -> global
#pragma unroll
    for (int o = 16; o; o >>= 1) mx = fmaxf(mx, __shfl_xor_sync(0xffffffffu, mx, o));
    if ((tid & 31) == 0) s_wmax[tid >> 5] = mx;
    __syncthreads();
    if (tid == 0) {
        float bm = s_wmax[0];
#pragma unroll
        for (int w = 1; w < 8; w++) bm = fmaxf(bm, s_wmax[w]);
        atomicMax(&d_maxbits, __float_as_uint(bm));   // positive floats: uint order == float order
    }
}

// ---------------- persistent Sinkhorn -------------------------------------
// grid 128 x 1024 (single wave on 148 SMs). 8 blocks per batch, warp = 4 rows.
#define SK_GRID 128

__device__ __forceinline__ void grid_barrier(unsigned target) {
    __syncthreads();
    if (threadIdx.x == 0) {
        __threadfence();
        atomicAdd(&d_barcnt, 1u);
        while (*((volatile unsigned*)&d_barcnt) < target) { }
        __threadfence();
    }
    __syncthreads();
}

__device__ __forceinline__ void dot4(const __half* __restrict__ rowbase,
                                     const float* __restrict__ sv, int lane,
                                     float& s0, float& s1, float& s2, float& s3) {
    const uint4* r = (const uint4*)rowbase;   // 128 uint4 per row
    float a0 = 0.f, a1 = 0.f, a2 = 0.f, a3 = 0.f;
#pragma unroll
    for (int k = 0; k < 4; k++) {
        int idx = lane + 32 * k;
        float4 va = *(const float4*)(sv + idx * 8);
        float4 vb = *(const float4*)(sv + idx * 8 + 4);
        uint4 q0 = r[idx];
        uint4 q1 = r[idx + 128];
        uint4 q2 = r[idx + 256];
        uint4 q3 = r[idx + 384];
#define DOT8(q, acc)                                                         \
        {                                                                    \
            float2 f0 = __half22float2(*(__half2*)&q.x);                     \
            float2 f1 = __half22float2(*(__half2*)&q.y);                     \
            float2 f2 = __half22float2(*(__half2*)&q.z);                     \
            float2 f3 = __half22float2(*(__half2*)&q.w);                     \
            acc = fmaf(f0.x, va.x, acc); acc = fmaf(f0.y, va.y, acc);        \
            acc = fmaf(f1.x, va.z, acc); acc = fmaf(f1.y, va.w, acc);        \
            acc = fmaf(f2.x, vb.x, acc); acc = fmaf(f2.y, vb.y, acc);        \
            acc = fmaf(f3.x, vb.z, acc); acc = fmaf(f3.y, vb.w, acc);        \
        }
        DOT8(q0, a0) DOT8(q1, a1) DOT8(q2, a2) DOT8(q3, a3)
#undef DOT8
    }
    s0 = a0; s1 = a1; s2 = a2; s3 = a3;
}

__global__ void __launch_bounds__(1024, 1)
sinkhorn_kernel(float* __restrict__ out) {
    __shared__ __align__(16) float sv[NPTS];
    __shared__ float s_block;

    const int tid   = threadIdx.x;
    const int warp  = tid >> 5;
    const int lane  = tid & 31;
    const int blk   = blockIdx.x;       // 0..127
    const int batch = blk >> 3;
    const int wb    = blk & 7;
    const int row0  = wb * 128 + warp * 4;

    const float invM = 1.0f / __uint_as_float(d_maxbits);
    const __half* Cb  = d_C  + ((size_t)batch << 20);
    const __half* CTb = d_CT + ((size_t)batch << 20);
    float* ub = d_u + batch * NPTS;
    float* vb = d_v + batch * NPTS;

    unsigned step = 0;
    for (int iter = 0; iter < MAXIT; iter++) {
        // ---- u = 1 / (invM * (C v) + eps)
        sv[tid] = __ldcg(vb + tid);
        __syncthreads();
        float s0, s1, s2, s3;
        dot4(Cb + (size_t)row0 * NPTS, sv, lane, s0, s1, s2, s3);
#pragma unroll
        for (int o = 16; o; o >>= 1) {
            s0 += __shfl_xor_sync(0xffffffffu, s0, o);
            s1 += __shfl_xor_sync(0xffffffffu, s1, o);
            s2 += __shfl_xor_sync(0xffffffffu, s2, o);
            s3 += __shfl_xor_sync(0xffffffffu, s3, o);
        }
        if (lane < 4) {
            float s = (lane == 0) ? s0 : (lane == 1) ? s1 : (lane == 2) ? s2 : s3;
            ub[row0 + lane] = 1.0f / (fmaf(invM, s, EPS_SK));
        }
        grid_barrier(SK_GRID * (++step));

        // ---- v = 1 / (invM * (C^T u) + eps)
        sv[tid] = __ldcg(ub + tid);
        __syncthreads();
        dot4(CTb + (size_t)row0 * NPTS, sv, lane, s0, s1, s2, s3);
#pragma unroll
        for (int o = 16; o; o >>= 1) {
            s0 += __shfl_xor_sync(0xffffffffu, s0, o);
            s1 += __shfl_xor_sync(0xffffffffu, s1, o);
            s2 += __shfl_xor_sync(0xffffffffu, s2, o);
            s3 += __shfl_xor_sync(0xffffffffu, s3, o);
        }
        if (lane < 4) {
            float s = (lane == 0) ? s0 : (lane == 1) ? s1 : (lane == 2) ? s2 : s3;
            vb[row0 + lane] = 1.0f / (fmaf(invM, s, EPS_SK));
        }
        grid_barrier(SK_GRID * (++step));
    }

    // ---- distance_b = invM * sum_n u[n] * (C v)[n]; out = mean over batches
    if (tid == 0) s_block = 0.0f;
    sv[tid] = __ldcg(vb + tid);
    __syncthreads();
    float s0, s1, s2, s3;
    dot4(Cb + (size_t)row0 * NPTS, sv, lane, s0, s1, s2, s3);
#pragma unroll
    for (int o = 16; o; o >>= 1) {
        s0 += __shfl_xor_sync(0xffffffffu, s0, o);
        s1 += __shfl_xor_sync(0xffffffffu, s1, o);
        s2 += __shfl_xor_sync(0xffffffffu, s2, o);
        s3 += __shfl_xor_sync(0xffffffffu, s3, o);
    }
    if (lane == 0) {
        float c = invM * (__ldcg(ub + row0 + 0) * s0 + __ldcg(ub + row0 + 1) * s1 +
                          __ldcg(ub + row0 + 2) * s2 + __ldcg(ub + row0 + 3) * s3);
        atomicAdd(&s_block, c);
    }
    __syncthreads();
    if (tid == 0) atomicAdd(out, s_block * (1.0f / BATCHES));
}

// ---------------- launch ----------------------------------------------------
extern "C" void kernel_launch(void* const* d_in, const int* in_sizes, int n_in,
                              void* d_out, int out_size) {
    (void)in_sizes; (void)n_in; (void)out_size;
    const float* x = (const float*)d_in[0];
    const float* y = (const float*)d_in[1];
    float* out = (float*)d_out;

    init_kernel<<<32, 1024>>>(out);
    norm_kernel<<<4096, 256>>>(x, y);
    dim3 g(8, 8, 16);   // (m-tiles, n-tiles, batch)
    gemm_cost_kernel<<<g, 256>>>(x, y);
    sinkhorn_kernel<<<SK_GRID, 1024>>>(out);
}

// round 2
// speedup vs baseline: 1.7338x; 1.7338x over previous
#include <cuda_runtime.h>
#include <cuda_fp16.h>
#include <cstdint>

#define BATCHES 16
#define NPTS    1024
#define DIMS    1024
#define EPS_SK  1e-3f
#define MAXIT   100

// ---------------- scratch (static device globals; no runtime alloc) --------
__device__ __half  d_C [BATCHES * NPTS * NPTS];   // C[b][n][m]  (32 MB)
__device__ __half  d_CT[BATCHES * NPTS * NPTS];   // C^T[b][m][n] (32 MB)
__device__ __half  d_xh[BATCHES * NPTS * DIMS];   // normalized x, fp16 (32 MB)
__device__ __half  d_yh[BATCHES * NPTS * DIMS];   // normalized y, fp16 (32 MB)
__device__ float   d_u[BATCHES * NPTS];
__device__ float   d_v[BATCHES * NPTS];
__device__ unsigned d_maxbits;                    // positive-float max as bits
__device__ unsigned d_bar[BATCHES * 32];          // per-batch barrier counters (128B apart)

// ---------------- init: reset per-replay state -----------------------------
__global__ void init_kernel(float* out) {
    int i = blockIdx.x * blockDim.x + threadIdx.x;
    if (i < BATCHES * NPTS) {
        d_u[i] = 1.0f / NPTS;
        d_v[i] = 1.0f / NPTS;
    }
    if (i < BATCHES * 32) d_bar[i] = 0u;
    if (i == 0) {
        d_maxbits = 0u;
        out[0]    = 0.0f;
    }
}

// ---------------- normalize rows and convert to fp16 -----------------------
// warp per row; rows 0..16383 -> x, 16384..32767 -> y
__global__ void normc_kernel(const float* __restrict__ x,
                             const float* __restrict__ y) {
    int gw   = blockIdx.x * 8 + (threadIdx.x >> 5);
    int lane = threadIdx.x & 31;
    const float* src;
    __half* dst;
    if (gw < BATCHES * NPTS) { src = x + (size_t)gw * DIMS;                     dst = d_xh + (size_t)gw * DIMS; }
    else                     { src = y + (size_t)(gw - BATCHES * NPTS) * DIMS;  dst = d_yh + (size_t)(gw - BATCHES * NPTS) * DIMS; }
    const float4* p = (const float4*)src;
    float4 f[8];
    float ss = 0.0f;
#pragma unroll
    for (int k = 0; k < 8; k++) {
        f[k] = p[lane + 32 * k];
        ss += f[k].x * f[k].x + f[k].y * f[k].y + f[k].z * f[k].z + f[k].w * f[k].w;
    }
#pragma unroll
    for (int o = 16; o; o >>= 1) ss += __shfl_xor_sync(0xffffffffu, ss, o);
    float inv = 1.0f / fmaxf(sqrtf(ss), 1e-12f);
#pragma unroll
    for (int k = 0; k < 8; k++) {
        __half2 h0 = __floats2half2_rn(f[k].x * inv, f[k].y * inv);
        __half2 h1 = __floats2half2_rn(f[k].z * inv, f[k].w * inv);
        uint2 u; u.x = *(unsigned*)&h0; u.y = *(unsigned*)&h1;
        *(uint2*)(dst + (size_t)(lane + 32 * k) * 4) = u;
    }
}

// ---------------- tensor-core cost GEMM ------------------------------------
// C[b][n][m] = 1 - xh[b][n] . yh[b][m]   via mma.sync m16n8k16 (fp16 in, f32 acc)
// Block: 256 thr (8 warps), tile 128(n) x 128(m), k-step 32, double-buffered.
#define SSTRIDE 40   // smem row stride in halves (conflict-free fragment reads)
#define CTSTR   136  // output staging stride in halves (16B-aligned rows)

__device__ __forceinline__ void mma16816(float* d, const unsigned* a, const unsigned* b) {
    asm volatile(
        "mma.sync.aligned.m16n8k16.row.col.f32.f16.f16.f32 "
        "{%0,%1,%2,%3}, {%4,%5,%6,%7}, {%8,%9}, {%0,%1,%2,%3};"
        : "+f"(d[0]), "+f"(d[1]), "+f"(d[2]), "+f"(d[3])
        : "r"(a[0]), "r"(a[1]), "r"(a[2]), "r"(a[3]), "r"(b[0]), "r"(b[1]));
}

__global__ void __launch_bounds__(256, 1)
gemm_cost_mma(void) {
    __shared__ __align__(16) __half smem_all[4 * 128 * SSTRIDE];
    __shared__ float s_wmax[8];
    // layout: A stage s -> smem_all + s*5120 ; B stage s -> smem_all + 10240 + s*5120

    const int tid  = threadIdx.x;
    const int warp = tid >> 5;
    const int lane = tid & 31;
    const int wm   = warp >> 2;          // 0..1 : 64-row slab (n-dim)
    const int wn   = warp & 3;           // 0..3 : 32-col slab (m-dim)
    const int lq   = lane >> 2;          // 0..7
    const int lr4  = lane & 3;           // 0..3
    const int bz   = blockIdx.z;
    const int n0   = blockIdx.y * 128;
    const int m0   = blockIdx.x * 128;

    const int lr = tid >> 1;             // load row 0..127
    const int lc = (tid & 1) * 16;       // halves 0 or 16
    const __half* xg = d_xh + ((size_t)bz << 20) + (size_t)(n0 + lr) * DIMS + lc;
    const __half* yg = d_yh + ((size_t)bz << 20) + (size_t)(m0 + lr) * DIMS + lc;

    float acc[4][4][4];
#pragma unroll
    for (int i = 0; i < 4; i++)
#pragma unroll
        for (int j = 0; j < 4; j++)
#pragma unroll
            for (int q = 0; q < 4; q++) acc[i][j][q] = 0.0f;

    // prologue: stage 0
    uint4 xa0 = *(const uint4*)(xg);
    uint4 xa1 = *(const uint4*)(xg + 8);
    uint4 ya0 = *(const uint4*)(yg);
    uint4 ya1 = *(const uint4*)(yg + 8);
    {
        __half* As = smem_all;
        __half* Bs = smem_all + 2 * 128 * SSTRIDE;
        *(uint4*)(As + lr * SSTRIDE + lc)     = xa0;
        *(uint4*)(As + lr * SSTRIDE + lc + 8) = xa1;
        *(uint4*)(Bs + lr * SSTRIDE + lc)     = ya0;
        *(uint4*)(Bs + lr * SSTRIDE + lc + 8) = ya1;
    }
    __syncthreads();

    for (int it = 0; it < 32; it++) {
        const int cur = it & 1;
        if (it < 31) {
            const int k0 = (it + 1) * 32;
            xa0 = *(const uint4*)(xg + k0);
            xa1 = *(const uint4*)(xg + k0 + 8);
            ya0 = *(const uint4*)(yg + k0);
            ya1 = *(const uint4*)(yg + k0 + 8);
        }
        const __half* As = smem_all + cur * 128 * SSTRIDE;
        const __half* Bs = smem_all + (2 + cur) * 128 * SSTRIDE;
#pragma unroll
        for (int ks = 0; ks < 32; ks += 16) {
            unsigned a[4][4], b[4][2];
#pragma unroll
            for (int i = 0; i < 4; i++) {
                const __half* ap = As + (wm * 64 + i * 16 + lq) * SSTRIDE + ks + lr4 * 2;
                a[i][0] = *(const unsigned*)(ap);
                a[i][1] = *(const unsigned*)(ap + 8 * SSTRIDE);
                a[i][2] = *(const unsigned*)(ap + 8);
                a[i][3] = *(const unsigned*)(ap + 8 * SSTRIDE + 8);
            }
#pragma unroll
            for (int j = 0; j < 4; j++) {
                const __half* bp = Bs + (wn * 32 + j * 8 + lq) * SSTRIDE + ks + lr4 * 2;
                b[j][0] = *(const unsigned*)(bp);
                b[j][1] = *(const unsigned*)(bp + 8);
            }
#pragma unroll
            for (int i = 0; i < 4; i++)
#pragma unroll
                for (int j = 0; j < 4; j++) mma16816(acc[i][j], a[i], b[j]);
        }
        if (it < 31) {
            const int nxt = (it + 1) & 1;
            __half* Asn = smem_all + nxt * 128 * SSTRIDE;
            __half* Bsn = smem_all + (2 + nxt) * 128 * SSTRIDE;
            *(uint4*)(Asn + lr * SSTRIDE + lc)     = xa0;
            *(uint4*)(Asn + lr * SSTRIDE + lc + 8) = xa1;
            *(uint4*)(Bsn + lr * SSTRIDE + lc)     = ya0;
            *(uint4*)(Bsn + lr * SSTRIDE + lc + 8) = ya1;
        }
        __syncthreads();
    }

    // epilogue: cost = 1 - dot; stage into smem, then coalesced C + CT writes
    __half* Ct = smem_all;   // 128 x CTSTR halves (34816 B, fits in 40960 B)
    float mx = 0.0f;
#pragma unroll
    for (int i = 0; i < 4; i++) {
        const int r0 = wm * 64 + i * 16 + lq;
#pragma unroll
        for (int j = 0; j < 4; j++) {
            const int c = wn * 32 + j * 8 + lr4 * 2;
            float c00 = 1.0f - acc[i][j][0];
            float c01 = 1.0f - acc[i][j][1];
            float c10 = 1.0f - acc[i][j][2];
            float c11 = 1.0f - acc[i][j][3];
            mx = fmaxf(mx, fmaxf(fmaxf(c00, c01), fmaxf(c10, c11)));
            *(__half2*)(Ct + r0 * CTSTR + c)       = __floats2half2_rn(c00, c01);
            *(__half2*)(Ct + (r0 + 8) * CTSTR + c) = __floats2half2_rn(c10, c11);
        }
    }
    __syncthreads();

    const size_t base = (size_t)bz << 20;
    {   // C rows: thread -> row=tid>>1, 64-half chunk
        const int row = tid >> 1;
        const int off = (tid & 1) * 64;
#pragma unroll
        for (int u = 0; u < 8; u++) {
            uint4 q = *(const uint4*)(Ct + row * CTSTR + off + u * 8);
            *(uint4*)(d_C + base + (size_t)(n0 + row) * NPTS + m0 + off + u * 8) = q;
        }
    }
    {   // CT rows: gather column m across n
        const int m = tid >> 1;
        const int off = (tid & 1) * 64;
#pragma unroll
        for (int u = 0; u < 8; u++) {
            __half2 h[4];
#pragma unroll
            for (int p = 0; p < 4; p++) {
                __half lo = Ct[(off + u * 8 + 2 * p)     * CTSTR + m];
                __half hi = Ct[(off + u * 8 + 2 * p + 1) * CTSTR + m];
                h[p] = __halves2half2(lo, hi);
            }
            uint4 q; q.x = *(unsigned*)&h[0]; q.y = *(unsigned*)&h[1];
            q.z = *(unsigned*)&h[2]; q.w = *(unsigned*)&h[3];
            *(uint4*)(d_CT + base + (size_t)m * NPTS + n0 + off + u * 8) = q;
        }
    }

    // block max -> global
#pragma unroll
    for (int o = 16; o; o >>= 1) mx = fmaxf(mx, __shfl_xor_sync(0xffffffffu, mx, o));
    if (lane == 0) s_wmax[warp] = mx;
    __syncthreads();
    if (tid == 0) {
        float bm = s_wmax[0];
#pragma unroll
        for (int w = 1; w < 8; w++) bm = fmaxf(bm, s_wmax[w]);
        atomicMax(&d_maxbits, __float_as_uint(bm));
    }
}

// ---------------- persistent Sinkhorn -------------------------------------
// grid 128 x 1024, 8 blocks per batch, per-batch barriers, HFMA2 matvec.
#define SK_GRID 128
#define BLK_PER_B 8

__device__ __forceinline__ void batch_barrier(int batch, unsigned target) {
    __syncthreads();
    if (threadIdx.x == 0) {
        __threadfence();
        unsigned* ctr = &d_bar[batch * 32];
        atomicAdd(ctr, 1u);
        while (*((volatile unsigned*)ctr) < target) { }
        __threadfence();
    }
    __syncthreads();
}

__device__ __forceinline__ __half2 h2u(unsigned u) { return *(__half2*)&u; }

// warp computes 4 consecutive row dot-products in half2, returns fp32 sums
__device__ __forceinline__ void dot4h(const __half* __restrict__ rowbase,
                                      const __half2* __restrict__ sv2, int lane,
                                      float& s0, float& s1, float& s2, float& s3) {
    const uint4* r = (const uint4*)rowbase;   // 128 uint4 per row
    __half2 z = __floats2half2_rn(0.f, 0.f);
    __half2 a0a = z, a0b = z, a1a = z, a1b = z, a2a = z, a2b = z, a3a = z, a3b = z;
#pragma unroll
    for (int k = 0; k < 4; k++) {
        int idx = lane + 32 * k;
        uint4 vv = *(const uint4*)(sv2 + idx * 4);
        __half2 v0 = h2u(vv.x), v1 = h2u(vv.y), v2 = h2u(vv.z), v3 = h2u(vv.w);
        uint4 q0 = r[idx];
        uint4 q1 = r[idx + 128];
        uint4 q2 = r[idx + 256];
        uint4 q3 = r[idx + 384];
        a0a = __hfma2(h2u(q0.x), v0, a0a); a0b = __hfma2(h2u(q0.y), v1, a0b);
        a0a = __hfma2(h2u(q0.z), v2, a0a); a0b = __hfma2(h2u(q0.w), v3, a0b);
        a1a = __hfma2(h2u(q1.x), v0, a1a); a1b = __hfma2(h2u(q1.y), v1, a1b);
        a1a = __hfma2(h2u(q1.z), v2, a1a); a1b = __hfma2(h2u(q1.w), v3, a1b);
        a2a = __hfma2(h2u(q2.x), v0, a2a); a2b = __hfma2(h2u(q2.y), v1, a2b);
        a2a = __hfma2(h2u(q2.z), v2, a2a); a2b = __hfma2(h2u(q2.w), v3, a2b);
        a3a = __hfma2(h2u(q3.x), v0, a3a); a3b = __hfma2(h2u(q3.y), v1, a3b);
        a3a = __hfma2(h2u(q3.z), v2, a3a); a3b = __hfma2(h2u(q3.w), v3, a3b);
    }
    s0 = __low2float(a0a) + __high2float(a0a) + __low2float(a0b) + __high2float(a0b);
    s1 = __low2float(a1a) + __high2float(a1a) + __low2float(a1b) + __high2float(a1b);
    s2 = __low2float(a2a) + __high2float(a2a) + __low2float(a2b) + __high2float(a2b);
    s3 = __low2float(a3a) + __high2float(a3a) + __low2float(a3b) + __high2float(a3b);
}

__global__ void __launch_bounds__(1024, 1)
sinkhorn_kernel(float* __restrict__ out) {
    __shared__ __align__(16) __half2 sv2[NPTS / 2];
    __shared__ float s_block;

    const int tid   = threadIdx.x;
    const int warp  = tid >> 5;
    const int lane  = tid & 31;
    const int blk   = blockIdx.x;            // 0..127
    const int batch = blk >> 3;
    const int wb    = blk & 7;
    const int row0  = wb * 128 + warp * 4;

    const float invM = 1.0f / __uint_as_float(d_maxbits);
    const __half* Cb  = d_C  + ((size_t)batch << 20);
    const __half* CTb = d_CT + ((size_t)batch << 20);
    float* ub = d_u + batch * NPTS;
    float* vb = d_v + batch * NPTS;

    unsigned step = 0;
    for (int iter = 0; iter < MAXIT; iter++) {
        // ---- u = 1 / (invM * (C v) + eps)
        if (tid < NPTS / 2) {
            float2 f = __ldcg((const float2*)(vb + 2 * tid));
            sv2[tid] = __floats2half2_rn(f.x, f.y);
        }
        __syncthreads();
        float s0, s1, s2, s3;
        dot4h(Cb + (size_t)row0 * NPTS, sv2, lane, s0, s1, s2, s3);
#pragma unroll
        for (int o = 16; o; o >>= 1) {
            s0 += __shfl_xor_sync(0xffffffffu, s0, o);
            s1 += __shfl_xor_sync(0xffffffffu, s1, o);
            s2 += __shfl_xor_sync(0xffffffffu, s2, o);
            s3 += __shfl_xor_sync(0xffffffffu, s3, o);
        }
        if (lane < 4) {
            float s = (lane == 0) ? s0 : (lane == 1) ? s1 : (lane == 2) ? s2 : s3;
            ub[row0 + lane] = 1.0f / (fmaf(invM, s, EPS_SK));
        }
        batch_barrier(batch, BLK_PER_B * (++step));

        // ---- v = 1 / (invM * (C^T u) + eps)
        if (tid < NPTS / 2) {
            float2 f = __ldcg((const float2*)(ub + 2 * tid));
            sv2[tid] = __floats2half2_rn(f.x, f.y);
        }
        __syncthreads();
        dot4h(CTb + (size_t)row0 * NPTS, sv2, lane, s0, s1, s2, s3);
#pragma unroll
        for (int o = 16; o; o >>= 1) {
            s0 += __shfl_xor_sync(0xffffffffu, s0, o);
            s1 += __shfl_xor_sync(0xffffffffu, s1, o);
            s2 += __shfl_xor_sync(0xffffffffu, s2, o);
            s3 += __shfl_xor_sync(0xffffffffu, s3, o);
        }
        if (lane < 4) {
            float s = (lane == 0) ? s0 : (lane == 1) ? s1 : (lane == 2) ? s2 : s3;
            vb[row0 + lane] = 1.0f / (fmaf(invM, s, EPS_SK));
        }
        batch_barrier(batch, BLK_PER_B * (++step));
    }

    // ---- distance_b = invM * sum_n u[n] * (C v)[n]; out = mean over batches
    if (tid == 0) s_block = 0.0f;
    if (tid < NPTS / 2) {
        float2 f = __ldcg((const float2*)(vb + 2 * tid));
        sv2[tid] = __floats2half2_rn(f.x, f.y);
    }
    __syncthreads();
    float s0, s1, s2, s3;
    dot4h(Cb + (size_t)row0 * NPTS, sv2, lane, s0, s1, s2, s3);
#pragma unroll
    for (int o = 16; o; o >>= 1) {
        s0 += __shfl_xor_sync(0xffffffffu, s0, o);
        s1 += __shfl_xor_sync(0xffffffffu, s1, o);
        s2 += __shfl_xor_sync(0xffffffffu, s2, o);
        s3 += __shfl_xor_sync(0xffffffffu, s3, o);
    }
    if (lane == 0) {
        float c = invM * (__ldcg(ub + row0 + 0) * s0 + __ldcg(ub + row0 + 1) * s1 +
                          __ldcg(ub + row0 + 2) * s2 + __ldcg(ub + row0 + 3) * s3);
        atomicAdd(&s_block, c);
    }
    __syncthreads();
    if (tid == 0) atomicAdd(out, s_block * (1.0f / BATCHES));
}

// ---------------- launch ----------------------------------------------------
extern "C" void kernel_launch(void* const* d_in, const int* in_sizes, int n_in,
                              void* d_out, int out_size) {
    (void)in_sizes; (void)n_in; (void)out_size;
    const float* x = (const float*)d_in[0];
    const float* y = (const float*)d_in[1];
    float* out = (float*)d_out;

    init_kernel<<<32, 1024>>>(out);
    normc_kernel<<<4096, 256>>>(x, y);
    dim3 g(8, 8, 16);   // (m-tiles, n-tiles, batch)
    gemm_cost_mma<<<g, 256>>>();
    sinkhorn_kernel<<<SK_GRID, 1024>>>(out);
}